// round 10
// baseline (speedup 1.0000x reference)
#include <cuda_runtime.h>
#include <cuda_fp16.h>
#include <cstdint>

#define B   32
#define C   128
#define H   64
#define W   64
#define KM  4
#define O   256
#define RED 32
#define HW  4096
#define KDIM 1152
#define NT  1024      // 32x32 output tiles of 2x2 per image

// ---------------- device scratch (module globals, no allocation) ------------
__device__ float g_pooled[B * C];
__device__ float g_att[B * KM];
__device__ __align__(256) __half g_xt[(size_t)B * HW * C];        // [b][pix][c]
__device__ __align__(256) __half g_u[(size_t)B * 16 * O * C];     // [b][xv][o][c]
__device__ __align__(256) __half g_v[(size_t)B * 16 * NT * C];    // [b][xv][t][c]

// ---------------- PTX helpers (family-independent) -------------
__device__ __forceinline__ uint32_t smem_to_u32(const void* p) {
    uint32_t a;
    asm("{ .reg .u64 t; cvta.to.shared.u64 t, %1; cvt.u32.u64 %0, t; }" : "=r"(a) : "l"(p));
    return a;
}
__device__ __forceinline__ void cp_bulk(uint32_t dst, const void* src, uint32_t bytes, uint32_t mbar) {
    asm volatile("cp.async.bulk.shared::cta.global.mbarrier::complete_tx::bytes [%0], [%1], %2, [%3];"
        :: "r"(dst), "l"(src), "r"(bytes), "r"(mbar) : "memory");
}
#define MBARRIER_INIT(mbar, c) \
    asm volatile("mbarrier.init.shared.b64 [%0], %1;" :: "r"((uint32_t)(mbar)), "r"((uint32_t)(c)) : "memory")
#define MBARRIER_INVAL(mbar) \
    asm volatile("mbarrier.inval.shared.b64 [%0];" :: "r"((uint32_t)(mbar)) : "memory")
#define MBARRIER_ARRIVE_EXPECT_TX(mbar, bytes) \
    asm volatile("mbarrier.arrive.expect_tx.shared.b64 _, [%0], %1;" \
        :: "r"((uint32_t)(mbar)), "r"((uint32_t)(bytes)) : "memory")
#define FENCE_PROXY_ASYNC() asm volatile("fence.proxy.async.shared::cta;" ::: "memory")

#define MBARRIER_WAIT_PARITY(mbar_smem_addr, phase_parity) do { \
    uint32_t _mbar = (uint32_t)(mbar_smem_addr); \
    uint32_t _parity = (uint32_t)(phase_parity); \
    uint32_t _done; \
    asm volatile("{\n\t.reg .pred p;\n\t" \
        "mbarrier.try_wait.parity.acquire.cta.shared::cta.b64 p, [%1], %2;\n\t" \
        "selp.b32 %0, 1, 0, p;\n\t}" \
        : "=r"(_done) : "r"(_mbar), "r"(_parity) : "memory"); \
    if (!_done) { \
        asm volatile("{\n\t.reg .pred P1;\n\t" \
            "WAIT_LOOP_%=:\n\t" \
            "mbarrier.try_wait.parity.acquire.cta.shared::cta.b64 P1, [%0], %1, 0x989680;\n\t" \
            "@P1 bra.uni WAIT_DONE_%=;\n\t" \
            "bra.uni WAIT_LOOP_%=;\n\t" \
            "WAIT_DONE_%=:\n\t}" \
            :: "r"(_mbar), "r"(_parity) : "memory"); \
    } \
} while(0)

#define LDSM_X4(r, addr) \
    asm volatile("ldmatrix.sync.aligned.m8n8.x4.shared.b16 {%0,%1,%2,%3}, [%4];" \
        : "=r"((r)[0]), "=r"((r)[1]), "=r"((r)[2]), "=r"((r)[3]) : "r"(addr))

__device__ __forceinline__ void mma16816(float* d, const uint32_t* a, uint32_t b0, uint32_t b1) {
    asm volatile("mma.sync.aligned.m16n8k16.row.col.f32.f16.f16.f32 "
        "{%0,%1,%2,%3}, {%4,%5,%6,%7}, {%8,%9}, {%0,%1,%2,%3};"
        : "+f"(d[0]), "+f"(d[1]), "+f"(d[2]), "+f"(d[3])
        : "r"(a[0]), "r"(a[1]), "r"(a[2]), "r"(a[3]), "r"(b0), "r"(b1));
}

// ---------------------------------------------------------------------------
// 0) zero pooled accumulator
// ---------------------------------------------------------------------------
__global__ void zero_kernel() {
    for (int i = threadIdx.x; i < B * C; i += 128) g_pooled[i] = 0.f;
}

// ---------------------------------------------------------------------------
// 1) x transpose -> xT[b][pix][c] fp16, fused with pooling partials
// ---------------------------------------------------------------------------
__global__ void xt_kernel(const float* __restrict__ x) {
    int b = blockIdx.y;
    int p0 = blockIdx.x * 64;
    __shared__ float sm[64][C + 1];
    const float* xb = x + (size_t)b * C * HW + p0;
    for (int idx = threadIdx.x; idx < 64 * C; idx += 256) {
        int c = idx >> 6, p = idx & 63;
        sm[p][c] = xb[(size_t)c * HW + p];
    }
    __syncthreads();
    __half* oh = g_xt + ((size_t)b * HW + p0) * C;
    for (int idx = threadIdx.x; idx < 64 * C; idx += 256) {
        int p = idx >> 7, c = idx & 127;
        oh[(size_t)p * C + c] = __float2half_rn(sm[p][c]);
    }
    if (threadIdx.x < C) {
        int c = threadIdx.x;
        float s = 0.f;
        #pragma unroll 8
        for (int p = 0; p < 64; p++) s += sm[p][c];
        atomicAdd(&g_pooled[b * C + c], s);
    }
}

// ---------------------------------------------------------------------------
// 2) Attention MLP + softmax (one thread per batch), pooled holds SUMS
// ---------------------------------------------------------------------------
__global__ void attn_kernel(const float* __restrict__ w1, const float* __restrict__ b1,
                            const float* __restrict__ w2, const float* __restrict__ b2) {
    int b = threadIdx.x;
    if (b >= B) return;
    const float inv_hw = 1.f / (float)HW;
    const float* pb = g_pooled + b * C;
    float h[RED];
    #pragma unroll 4
    for (int r = 0; r < RED; r++) {
        float s = 0.f;
        const float* wr = w1 + r * C;
        #pragma unroll 8
        for (int c = 0; c < C; c++) s += pb[c] * wr[c];
        h[r] = fmaxf(s * inv_hw + b1[r], 0.f);
    }
    float logits[KM];
    float mx = -1e30f;
    #pragma unroll
    for (int k = 0; k < KM; k++) {
        float s = b2[k];
        const float* wr = w2 + k * RED;
        #pragma unroll
        for (int r = 0; r < RED; r++) s += h[r] * wr[r];
        logits[k] = s; mx = fmaxf(mx, s);
    }
    float den = 0.f;
    #pragma unroll
    for (int k = 0; k < KM; k++) { logits[k] = __expf(logits[k] - mx); den += logits[k]; }
    float inv = 1.f / den;
    #pragma unroll
    for (int k = 0; k < KM; k++) g_att[b * KM + k] = logits[k] * inv;
}

// ---------------------------------------------------------------------------
// 3) U kernel: mix wk + Winograd filter transform U = G g G^T -> g_u
//    block (o, b), 128 threads, one channel per thread.
// ---------------------------------------------------------------------------
__global__ void u_kernel(const float* __restrict__ weights) {
    int o = blockIdx.x, b = blockIdx.y;
    int c = threadIdx.x;
    float a0 = g_att[b * KM + 0], a1 = g_att[b * KM + 1];
    float a2 = g_att[b * KM + 2], a3 = g_att[b * KM + 3];
    const size_t ks = (size_t)O * KDIM;
    const float* wp = weights + (size_t)o * KDIM + c * 9;
    float g[9];
    #pragma unroll
    for (int t = 0; t < 9; t++)
        g[t] = a0 * wp[t] + a1 * wp[ks + t] + a2 * wp[2 * ks + t] + a3 * wp[3 * ks + t];
    // rows: t0[xi][j] = (G g)[xi][j]
    float t0[4][3];
    #pragma unroll
    for (int j = 0; j < 3; j++) {
        t0[0][j] = g[j];
        t0[1][j] = 0.5f * (g[j] + g[3 + j] + g[6 + j]);
        t0[2][j] = 0.5f * (g[j] - g[3 + j] + g[6 + j]);
        t0[3][j] = g[6 + j];
    }
    __half* up = g_u + ((size_t)b * 16 * O + o) * C + c;
    const size_t ss = (size_t)O * C;
    #pragma unroll
    for (int xi = 0; xi < 4; xi++) {
        float u0 = t0[xi][0];
        float u1 = 0.5f * (t0[xi][0] + t0[xi][1] + t0[xi][2]);
        float u2 = 0.5f * (t0[xi][0] - t0[xi][1] + t0[xi][2]);
        float u3 = t0[xi][2];
        up[(xi * 4 + 0) * ss] = __float2half_rn(u0);
        up[(xi * 4 + 1) * ss] = __float2half_rn(u1);
        up[(xi * 4 + 2) * ss] = __float2half_rn(u2);
        up[(xi * 4 + 3) * ss] = __float2half_rn(u3);
    }
}

// ---------------------------------------------------------------------------
// 4) V kernel: input transform V = B^T d B per 4x4 patch (stride 2) -> g_v
//    block (ty, b), 256 threads.  smem = 4 rows x 66 px x 128 c fp16.
// ---------------------------------------------------------------------------
#define V_SMEM (4 * 66 * 128 * 2)   // 67584

__global__ void __launch_bounds__(256) v_kernel() {
    extern __shared__ __half sm[];   // [4][66][128], px shifted by +1
    int ty = blockIdx.x, b = blockIdx.y;
    int tid = threadIdx.x;

    // load 4 input rows (r = 2ty-1+i) into sm[i][1..64][*]; zero invalid rows
    #pragma unroll
    for (int i = 0; i < 4; i++) {
        int r = 2 * ty - 1 + i;
        uint4* dst = (uint4*)&sm[(i * 66 + 1) * 128];
        if ((unsigned)r < 64u) {
            const uint4* src = (const uint4*)(g_xt + ((size_t)b * HW + r * 64) * C);
            for (int q = tid; q < 1024; q += 256) dst[q] = src[q];
        } else {
            uint4 z = make_uint4(0, 0, 0, 0);
            for (int q = tid; q < 1024; q += 256) dst[q] = z;
        }
    }
    // zero edge px columns (px1 = 0 and 65)
    if (tid < 128) {
        int i = tid >> 5, which = (tid >> 4) & 1, q = tid & 15;
        uint4 z = make_uint4(0, 0, 0, 0);
        ((uint4*)&sm[(i * 66 + which * 65) * 128])[q] = z;
    }
    __syncthreads();

    int tx = tid >> 3;          // 0..31
    int cg = tid & 7;           // 0..7
    __half* vb = g_v + ((size_t)b * 16 * NT + ty * 32 + tx) * C;
    const size_t ss = (size_t)NT * C;

    #pragma unroll
    for (int cc2 = 0; cc2 < 4; cc2++) {
        int c0 = cg * 16 + cc2 * 4;
        // load d[i][j] as 2x half2 (4 channels)
        __half2 da[4][4], db[4][4];
        #pragma unroll
        for (int i = 0; i < 4; i++)
            #pragma unroll
            for (int j = 0; j < 4; j++) {
                uint2 w = *(const uint2*)&sm[(i * 66 + 2 * tx + j) * 128 + c0];
                da[i][j] = *(__half2*)&w.x;
                db[i][j] = *(__half2*)&w.y;
            }
        // row transform: e[xi][j]
        __half2 ea[4][4], eb[4][4];
        #pragma unroll
        for (int j = 0; j < 4; j++) {
            ea[0][j] = __hsub2(da[0][j], da[2][j]);
            ea[1][j] = __hadd2(da[1][j], da[2][j]);
            ea[2][j] = __hsub2(da[2][j], da[1][j]);
            ea[3][j] = __hsub2(da[1][j], da[3][j]);
            eb[0][j] = __hsub2(db[0][j], db[2][j]);
            eb[1][j] = __hadd2(db[1][j], db[2][j]);
            eb[2][j] = __hsub2(db[2][j], db[1][j]);
            eb[3][j] = __hsub2(db[1][j], db[3][j]);
        }
        // col transform + store per (xi,nu)
        #pragma unroll
        for (int xi = 0; xi < 4; xi++) {
            __half2 va[4], vbv[4];
            va[0] = __hsub2(ea[xi][0], ea[xi][2]);
            va[1] = __hadd2(ea[xi][1], ea[xi][2]);
            va[2] = __hsub2(ea[xi][2], ea[xi][1]);
            va[3] = __hsub2(ea[xi][1], ea[xi][3]);
            vbv[0] = __hsub2(eb[xi][0], eb[xi][2]);
            vbv[1] = __hadd2(eb[xi][1], eb[xi][2]);
            vbv[2] = __hsub2(eb[xi][2], eb[xi][1]);
            vbv[3] = __hsub2(eb[xi][1], eb[xi][3]);
            #pragma unroll
            for (int nu = 0; nu < 4; nu++) {
                uint2 w;
                w.x = *(uint32_t*)&va[nu];
                w.y = *(uint32_t*)&vbv[nu];
                *(uint2*)(vb + (size_t)(xi * 4 + nu) * ss + c0) = w;
            }
        }
    }
}

// ---------------------------------------------------------------------------
// 5) Winograd GEMM: 16 GEMMs (one per xv), M fold into Y in registers.
//    CTA: 32 o x 128 tiles, 256 threads (8 warps, 2x4), warp tile 16o x 32t.
// ---------------------------------------------------------------------------
#define RPADB 272
#define AT_BYTES (32 * RPADB)          // 8704
#define BT_BYTES (128 * RPADB)         // 34816
#define OFF_A 0
#define OFF_B AT_BYTES
#define STAGE_BYTES (AT_BYTES + BT_BYTES)   // 43520
#define STAGE_TX (160u * 256u)              // 40960
#define GEMM_SMEM (1024 + 2 * STAGE_BYTES)  // 88064

__global__ void __launch_bounds__(256, 2) wino_gemm(float* __restrict__ out) {
    extern __shared__ char smem[];
    uint32_t sb = smem_to_u32(smem);
    uint32_t mbar0 = sb;
    uint32_t tiles = sb + 1024;
    int tid = threadIdx.x;
    int lane = tid & 31, wid = tid >> 5;
    int b  = blockIdx.z;
    int ob = blockIdx.y * 32;
    int tb = blockIdx.x * 128;
    int wm = (wid & 1) * 16;
    int wn = (wid >> 1) * 32;

    if (tid == 0) { MBARRIER_INIT(mbar0, 1); MBARRIER_INIT(mbar0 + 8, 1); }
    __syncthreads();

    const __half* ub = g_u + ((size_t)b * 16 * O + ob) * C;
    const __half* vb = g_v + ((size_t)b * 16 * NT + tb) * C;

    auto load_stage = [&](int s) {
        uint32_t mbar = mbar0 + (uint32_t)(s & 1) * 8;
        uint32_t base = tiles + (uint32_t)(s & 1) * STAGE_BYTES;
        FENCE_PROXY_ASYNC();
        if (tid == 0) MBARRIER_ARRIVE_EXPECT_TX(mbar, STAGE_TX);
        __syncthreads();
        if (tid < 32) {
            cp_bulk(base + OFF_A + (uint32_t)tid * RPADB,
                    ub + ((size_t)s * O + tid) * C, 256, mbar);
        } else if (tid < 160) {
            int r = tid - 32;
            cp_bulk(base + OFF_B + (uint32_t)r * RPADB,
                    vb + ((size_t)s * NT + r) * C, 256, mbar);
        }
    };

    float Y[2][2][4][4];
    #pragma unroll
    for (int p = 0; p < 2; p++)
        #pragma unroll
        for (int q = 0; q < 2; q++)
            #pragma unroll
            for (int nt = 0; nt < 4; nt++)
                #pragma unroll
                for (int j = 0; j < 4; j++) Y[p][q][nt][j] = 0.f;

    load_stage(0);
    load_stage(1);

    uint32_t a_row = (uint32_t)(wm + (lane & 15));
    uint32_t a_kb  = (uint32_t)((lane >> 4) * 16);
    uint32_t b_row = (uint32_t)(wn + (lane & 7) + ((lane >> 4) & 1) * 8);
    uint32_t b_kb  = (uint32_t)(((lane >> 3) & 1) * 16);

    #pragma unroll
    for (int s = 0; s < 16; s++) {
        MBARRIER_WAIT_PARITY(mbar0 + (uint32_t)(s & 1) * 8, (s >> 1) & 1);
        uint32_t base = tiles + (uint32_t)(s & 1) * STAGE_BYTES;

        float M[4][4];
        #pragma unroll
        for (int nt = 0; nt < 4; nt++)
            #pragma unroll
            for (int j = 0; j < 4; j++) M[nt][j] = 0.f;

        #pragma unroll
        for (int kk = 0; kk < 8; kk++) {
            uint32_t kb = (uint32_t)(kk * 32);
            uint32_t a[4];
            LDSM_X4(a, base + OFF_A + a_row * RPADB + kb + a_kb);
            #pragma unroll
            for (int g = 0; g < 2; g++) {
                uint32_t bh[4];
                LDSM_X4(bh, base + OFF_B + (b_row + g * 16) * RPADB + kb + b_kb);
                mma16816(M[g * 2 + 0], a, bh[0], bh[1]);
                mma16816(M[g * 2 + 1], a, bh[2], bh[3]);
            }
        }

        // fold M(xi,nu) into Y with A^T coefficients (all 0/±1, compile-time)
        {
            const int xi = s >> 2, nu = s & 3;
            const float ax0 = (xi == 3) ? 0.f : 1.f;
            const float ax1 = (xi == 0) ? 0.f : ((xi == 1) ? 1.f : -1.f);
            const float an0 = (nu == 3) ? 0.f : 1.f;
            const float an1 = (nu == 0) ? 0.f : ((nu == 1) ? 1.f : -1.f);
            const float w00 = ax0 * an0, w01 = ax0 * an1;
            const float w10 = ax1 * an0, w11 = ax1 * an1;
            #pragma unroll
            for (int nt = 0; nt < 4; nt++)
                #pragma unroll
                for (int j = 0; j < 4; j++) {
                    float m = M[nt][j];
                    if (w00 != 0.f) Y[0][0][nt][j] += w00 * m;
                    if (w01 != 0.f) Y[0][1][nt][j] += w01 * m;
                    if (w10 != 0.f) Y[1][0][nt][j] += w10 * m;
                    if (w11 != 0.f) Y[1][1][nt][j] += w11 * m;
                }
        }
        __syncthreads();
        if (s + 2 < 16) load_stage(s + 2);
    }

    // epilogue: Y[p][q] -> out[b][o][2ty+p][2tx+2chat+q], float4 per (nt,rh,p)
    float* outb = out + (size_t)b * O * HW;
    int o0 = ob + wm + (lane >> 2);
    #pragma unroll
    for (int nt = 0; nt < 4; nt++) {
        int t0 = tb + wn + nt * 8 + 2 * (lane & 3);
        int ty = t0 >> 5, tx = t0 & 31;
        #pragma unroll
        for (int rh = 0; rh < 2; rh++) {
            int o = o0 + rh * 8;
            float* rowb = outb + (size_t)o * HW + 2 * tx;
            #pragma unroll
            for (int p = 0; p < 2; p++) {
                float4 v = make_float4(Y[p][0][nt][2 * rh],     Y[p][1][nt][2 * rh],
                                       Y[p][0][nt][2 * rh + 1], Y[p][1][nt][2 * rh + 1]);
                *(float4*)(rowb + (2 * ty + p) * 64) = v;
            }
        }
    }
    __syncthreads();
    if (tid == 0) { MBARRIER_INVAL(mbar0); MBARRIER_INVAL(mbar0 + 8); }
}

// ---------------------------------------------------------------------------
extern "C" void kernel_launch(void* const* d_in, const int* in_sizes, int n_in,
                              void* d_out, int out_size) {
    const float* x       = (const float*)d_in[0];
    const float* weights = (const float*)d_in[1];
    const float* w1      = (const float*)d_in[2];
    const float* b1      = (const float*)d_in[3];
    const float* w2      = (const float*)d_in[4];
    const float* b2      = (const float*)d_in[5];
    float* out = (float*)d_out;

    zero_kernel<<<1, 128>>>();
    xt_kernel<<<dim3(HW / 64, B), 256>>>(x);
    attn_kernel<<<1, 32>>>(w1, b1, w2, b2);
    u_kernel<<<dim3(O, B), 128>>>(weights);

    cudaFuncSetAttribute(v_kernel, cudaFuncAttributeMaxDynamicSharedMemorySize, V_SMEM);
    v_kernel<<<dim3(32, B), 256, V_SMEM>>>();

    cudaFuncSetAttribute(wino_gemm, cudaFuncAttributeMaxDynamicSharedMemorySize, GEMM_SMEM);
    wino_gemm<<<dim3(NT / 128, O / 32, B), 256, GEMM_SMEM>>>(out);
}